// round 13
// baseline (speedup 1.0000x reference)
#include <cuda_runtime.h>
#include <cuda_bf16.h>
#include <cstdint>

// Problem constants
#define LSEQ        103
#define V4_STRIDE   33                   // float4 row stride for s_d4/s_p4
#define DNA_C2      1648                 // float2 per dna chunk (8 batches * 4 * 103 / 2)
#define PROT_C2     2163                 // float2 per prot chunk (2 batches * 21 * 103 / 2)
#define N_CHUNKS    20                   // 4 dna + 16 prot
#define BUF_BYTES   17312                // padded chunk buffer (prot chunk = 17304 B)
#define SLAB_BYTES  (2 * BUF_BYTES)      // 34624 B dynamic smem (double buffer)

__device__ __forceinline__ void cp8(uint32_t dst, const void* src) {
    asm volatile("cp.async.ca.shared.global [%0], [%1], 8;" :: "r"(dst), "l"(src));
}

__global__ __launch_bounds__(256, 3)
void ma_block_kernel(const float* __restrict__ dna,
                     const float* __restrict__ prot,
                     const float* __restrict__ w_dna,
                     const float* __restrict__ w_prot,
                     const float* __restrict__ w_lin,
                     const float* __restrict__ b_lin,
                     float* __restrict__ out)
{
    extern __shared__ float s_slab[];            // [2][BUF_BYTES/4] double buffer
    __shared__ float4 s_d4[32 * V4_STRIDE];      // d triples: [k][m] = {d[3m],d[3m+1],d[3m+2],0}
    __shared__ float4 s_p4[32 * V4_STRIDE];      // p triples, same layout
    __shared__ float  s_wd[32];                  // (4,8)
    __shared__ float  s_wp[168];                 // (21,8)
    __shared__ float  s_wl[192];                 // (2,96)
    __shared__ float  s_bl[2];

    const int tid = threadIdx.x;
    const int u   = blockIdx.x;                  // 0..1023

    if (tid < 32)  s_wd[tid] = w_dna[tid];
    if (tid < 168) s_wp[tid] = w_prot[tid];
    if (tid < 192) s_wl[tid] = w_lin[tid];
    if (tid < 2)   s_bl[tid] = b_lin[tid];

    const float2* dna2  = reinterpret_cast<const float2*>(dna  + (size_t)u * (32 * 4  * LSEQ));
    const float2* prot2 = reinterpret_cast<const float2*>(prot + (size_t)u * (32 * 21 * LSEQ));
    const uint32_t sbase = (uint32_t)__cvta_generic_to_shared(s_slab);

    // Chunks 0..3: dna quarters (8 batches); 4..19: prot pairs (2 batches).
    auto issue = [&](int c, int bsel) {
        const uint32_t ba = sbase + (uint32_t)bsel * BUF_BYTES;
        if (c < 4) {
            const float2* src = dna2 + c * DNA_C2;
            for (int i = tid; i < DNA_C2; i += 256)
                cp8(ba + i * 8, src + i);
        } else {
            const float2* src = prot2 + (c - 4) * PROT_C2;
            for (int i = tid; i < PROT_C2; i += 256)
                cp8(ba + i * 8, src + i);
        }
        asm volatile("cp.async.commit_group;" ::: "memory");
    };

    // ---- dna chunk q (8 batches). warp = batch; lane: seg (16 x 6 cols), rs (2-way rows) ----
    auto compute_dna = [&](int q, const float* buf) {
        const int b8   = tid >> 5;               // 0..7 local batch
        const int lane = tid & 31;
        const int seg  = lane & 15;              // 0..15
        const int rs   = lane >> 4;              // 0..1 (rows 2rs, 2rs+1)
        const int j0   = seg * 6;

        float acc[6];
        #pragma unroll
        for (int jj = 0; jj < 6; jj++) acc[jj] = 0.f;

        #pragma unroll
        for (int i = 0; i < 2; i++) {
            const int r = rs * 2 + i;
            const float* srow = buf + (b8 * 4 + r) * LSEQ + j0;
            float win[13];
            #pragma unroll
            for (int x = 0; x < 13; x++) win[x] = srow[x];
            #pragma unroll
            for (int k = 0; k < 8; k++) {
                const float w = s_wd[r * 8 + k];
                #pragma unroll
                for (int jj = 0; jj < 6; jj++)
                    acc[jj] = fmaf(win[jj + k], w, acc[jj]);
            }
        }
        #pragma unroll
        for (int jj = 0; jj < 6; jj++)
            acc[jj] += __shfl_xor_sync(0xffffffffu, acc[jj], 16);
        if (rs == 0) {
            const int kk = q * 8 + b8;
            s_d4[kk * V4_STRIDE + seg * 2 + 0] =
                make_float4(fmaxf(acc[0], 0.f), fmaxf(acc[1], 0.f), fmaxf(acc[2], 0.f), 0.f);
            s_d4[kk * V4_STRIDE + seg * 2 + 1] =
                make_float4(fmaxf(acc[3], 0.f), fmaxf(acc[4], 0.f), fmaxf(acc[5], 0.f), 0.f);
        }
    };

    // ---- prot chunk g (2 batches). b = tid>>7; seg (16 x 6 cols); rs (8-way row split) ----
    // rows per rs: rs<5 -> 3 rows at 3*rs; rs>=5 -> 2 rows at 15+2*(rs-5). Total 21.
    auto compute_prot = [&](int g, const float* buf) {
        const int b    = tid >> 7;               // 0..1 local batch
        const int seg  = (tid >> 3) & 15;        // 0..15
        const int rs   = tid & 7;                // 0..7
        const int j0   = seg * 6;
        const int nrows = (rs < 5) ? 3 : 2;
        const int rbase = (rs < 5) ? 3 * rs : 15 + 2 * (rs - 5);

        float acc[6];
        #pragma unroll
        for (int jj = 0; jj < 6; jj++) acc[jj] = 0.f;

        #pragma unroll
        for (int i = 0; i < 3; i++) {
            if (i < nrows) {
                const int r = rbase + i;
                const float* srow = buf + (b * 21 + r) * LSEQ + j0;
                float win[13];
                #pragma unroll
                for (int x = 0; x < 13; x++) win[x] = srow[x];
                #pragma unroll
                for (int k = 0; k < 8; k++) {
                    const float w = s_wp[r * 8 + k];
                    #pragma unroll
                    for (int jj = 0; jj < 6; jj++)
                        acc[jj] = fmaf(win[jj + k], w, acc[jj]);
                }
            }
        }
        // combine 8 row-split partials (lane bits 0..2)
        #pragma unroll
        for (int jj = 0; jj < 6; jj++) {
            acc[jj] += __shfl_xor_sync(0xffffffffu, acc[jj], 1);
            acc[jj] += __shfl_xor_sync(0xffffffffu, acc[jj], 2);
            acc[jj] += __shfl_xor_sync(0xffffffffu, acc[jj], 4);
        }
        if (rs == 0) {
            const int kk = g * 2 + b;
            s_p4[kk * V4_STRIDE + seg * 2 + 0] =
                make_float4(fmaxf(acc[0], 0.f), fmaxf(acc[1], 0.f), fmaxf(acc[2], 0.f), 0.f);
            s_p4[kk * V4_STRIDE + seg * 2 + 1] =
                make_float4(fmaxf(acc[3], 0.f), fmaxf(acc[4], 0.f), fmaxf(acc[5], 0.f), 0.f);
        }
    };

    // ---------------- double-buffered pipeline over 20 chunks ----------------
    issue(0, 0);
    issue(1, 1);
    #pragma unroll 1
    for (int c = 0; c < N_CHUNKS; c++) {
        if (c < N_CHUNKS - 1) asm volatile("cp.async.wait_group 1;" ::: "memory");
        else                  asm volatile("cp.async.wait_group 0;" ::: "memory");
        __syncthreads();                         // chunk c visible to all threads
        const float* buf = s_slab + (c & 1) * (BUF_BYTES / 4);
        if (c < 4) compute_dna(c, buf);
        else       compute_prot(c - 4, buf);
        __syncthreads();                         // all readers of buf done
        if (c + 2 < N_CHUNKS) issue(c + 2, c & 1);
    }

    // ---------------- attention + linear (single fused pass, no max-sub) ----------------
    // Output b' = 1024*m + u: query = s_p4[lane][m], keys/values = s_d4[k][m].
    // softmax(lg*scale) without max subtraction: |lg*scale| << 88, no overflow possible.
    const int warp = tid >> 5;
    const int lane = tid & 31;

    const int jl = lane * 3;
    const float wl00 = s_wl[jl],      wl01 = s_wl[jl + 1],      wl02 = s_wl[jl + 2];
    const float wl10 = s_wl[96 + jl], wl11 = s_wl[96 + jl + 1], wl12 = s_wl[96 + jl + 2];

    #pragma unroll 1
    for (int mi = 0; mi < 4; mi++) {
        const int m = warp * 4 + mi;             // 0..31

        const float4 qv = s_p4[lane * V4_STRIDE + m];
        const float scale = 0.5773502691896258f; // 1/sqrt(3)
        const float q0 = qv.x * scale, q1 = qv.y * scale, q2 = qv.z * scale;

        float sum = 0.f, o0 = 0.f, o1 = 0.f, o2 = 0.f;
        #pragma unroll
        for (int k = 0; k < 32; k++) {
            const float4 v = s_d4[k * V4_STRIDE + m];   // broadcast LDS.128
            const float l = q0 * v.x + q1 * v.y + q2 * v.z;
            const float e = __expf(l);
            sum += e;
            o0 = fmaf(e, v.x, o0);
            o1 = fmaf(e, v.y, o1);
            o2 = fmaf(e, v.z, o2);
        }
        const float inv = 1.f / sum;
        o0 *= inv; o1 *= inv; o2 *= inv;

        float p0 = o0 * wl00 + o1 * wl01 + o2 * wl02;
        float p1 = o0 * wl10 + o1 * wl11 + o2 * wl12;

        #pragma unroll
        for (int off = 16; off > 0; off >>= 1) {
            p0 += __shfl_xor_sync(0xffffffffu, p0, off);
            p1 += __shfl_xor_sync(0xffffffffu, p1, off);
        }
        if (lane == 0) {
            const int b2 = m * 1024 + u;
            out[b2 * 2 + 0] = p0 + s_bl[0];
            out[b2 * 2 + 1] = p1 + s_bl[1];
        }
    }
}

extern "C" void kernel_launch(void* const* d_in, const int* in_sizes, int n_in,
                              void* d_out, int out_size)
{
    const float* dna    = (const float*)d_in[0];   // (32768,1,4,103)
    const float* prot   = (const float*)d_in[1];   // (32768,1,21,103)
    const float* w_dna  = (const float*)d_in[2];   // (1,1,4,8)
    const float* w_prot = (const float*)d_in[3];   // (1,1,21,8)
    const float* w_lin  = (const float*)d_in[4];   // (2,96)
    const float* b_lin  = (const float*)d_in[5];   // (2,)
    float* out = (float*)d_out;                    // (32768,1,2)

    cudaFuncSetAttribute(ma_block_kernel,
                         cudaFuncAttributeMaxDynamicSharedMemorySize,
                         (int)SLAB_BYTES);

    ma_block_kernel<<<1024, 256, SLAB_BYTES>>>(dna, prot, w_dna, w_prot, w_lin, b_lin, out);
}